// round 1
// baseline (speedup 1.0000x reference)
#include <cuda_runtime.h>
#include <math.h>

#define T_DAYS   10950
#define S_SITES  4000
#define N_YEARS  30
#define DAYS     365
#define NPAIRS   435   // 30*29/2
// order-stat element positions in the 512-sorted array (e = k*32 + lane):
// 364 -> (k=11, lane=12), 357 -> (11,5), 182 -> (5,22), 109 -> (3,13), 7 -> (0,7)
// median of 435 -> 217 -> (k=6, lane=25)

// ---------------- scratch (device globals; no allocations) ----------------
__device__ double g_sumsq;
__device__ double g_mean_trend;
__device__ double g_quant_trend;
__device__ float  g_pM[S_SITES * N_YEARS];
__device__ float  g_tM[S_SITES * N_YEARS];
__device__ float  g_pQ[S_SITES * N_YEARS * 5];
__device__ float  g_tQ[S_SITES * N_YEARS * 5];
__device__ int    g_pairI[NPAIRS];
__device__ int    g_pairJ[NPAIRS];

// ---------------- init: zero accumulators, build pair tables ----------------
__global__ void init_kernel() {
    if (threadIdx.x == 0) {
        g_sumsq = 0.0;
        g_mean_trend = 0.0;
        g_quant_trend = 0.0;
        int m = 0;
        for (int i = 0; i < N_YEARS; i++)
            for (int j = i + 1; j < N_YEARS; j++) {
                g_pairI[m] = i; g_pairJ[m] = j; m++;
            }
    }
}

// ---------------- warp bitonic sort of 512 (16 elems/thread) ----------------
// Element index e = k*32 + lane. Ascending overall. Pad with +INF.
__device__ __forceinline__ void bitonic512(float v[16], int lane) {
    #pragma unroll
    for (int size = 2; size <= 512; size <<= 1) {
        #pragma unroll
        for (int stride = size >> 1; stride > 0; stride >>= 1) {
            if (stride >= 32) {
                // in-register compare-exchange; direction depends only on k bits
                int ks = stride >> 5;
                #pragma unroll
                for (int k = 0; k < 16; k++) {
                    if ((k & ks) == 0) {
                        int k2 = k | ks;
                        bool up = (((k * 32) & size) == 0);
                        float a = v[k], b = v[k2];
                        float lo = fminf(a, b), hi = fmaxf(a, b);
                        v[k]  = up ? lo : hi;
                        v[k2] = up ? hi : lo;
                    }
                }
            } else {
                // cross-lane compare-exchange via shfl_xor
                #pragma unroll
                for (int k = 0; k < 16; k++) {
                    int e = k * 32 + lane;
                    float o = __shfl_xor_sync(0xffffffffu, v[k], stride);
                    bool keepmin = (((e & size) == 0) == ((lane & stride) == 0));
                    v[k] = keepmin ? fminf(v[k], o) : fmaxf(v[k], o);
                }
            }
        }
    }
}

// ---------------- kernel B: fused rmse + per-(site,year) sort/stats ----------------
// grid (S/32, 30); block 1024 threads (32 warps). Each block: one year, 32 sites.
// Dynamic shared: pred tile [365][33] + obs tile [365][33] (pad avoids bank conflicts).
__global__ void __launch_bounds__(1024, 2)
stats_kernel(const float* __restrict__ pred, const float* __restrict__ obs) {
    extern __shared__ float smem[];
    float* sp = smem;
    float* so = smem + DAYS * 33;

    const int tid  = threadIdx.x;
    const int lane = tid & 31;
    const int w    = tid >> 5;
    const int base = blockIdx.x * 32;
    const int year = blockIdx.y;

    // coalesced tile load + fused rmse partial
    float acc = 0.f;
    for (int i = tid; i < DAYS * 32; i += 1024) {
        int d = i >> 5, j = i & 31;
        int g = (year * DAYS + d) * S_SITES + base + j;
        float pv = pred[g], ov = obs[g];
        float df = pv - ov;
        acc += df * df;
        sp[d * 33 + j] = pv;
        so[d * 33 + j] = ov;
    }
    #pragma unroll
    for (int o = 16; o; o >>= 1) acc += __shfl_xor_sync(0xffffffffu, acc, o);
    __shared__ float red[32];
    if (lane == 0) red[w] = acc;
    __syncthreads();                       // tile ready + red ready
    if (w == 0) {
        float a = red[lane];
        #pragma unroll
        for (int o = 16; o; o >>= 1) a += __shfl_xor_sync(0xffffffffu, a, o);
        if (lane == 0) atomicAdd(&g_sumsq, (double)a);
    }

    const int site = base + w;
    const float INF = __int_as_float(0x7f800000);
    const int oMY = site * N_YEARS + year;

    // ---- pred series for this site ----
    {
        float v[16]; float sum = 0.f;
        #pragma unroll
        for (int k = 0; k < 16; k++) {
            int e = k * 32 + lane;
            float x = (e < DAYS) ? sp[e * 33 + w] : INF;
            v[k] = x;
            if (e < DAYS) sum += x;
        }
        #pragma unroll
        for (int o = 16; o; o >>= 1) sum += __shfl_xor_sync(0xffffffffu, sum, o);
        if (lane == 0) g_pM[oMY] = sum / (float)DAYS;
        bitonic512(v, lane);
        float* q = &g_pQ[oMY * 5];
        if (lane == 12) q[0] = v[11];   // idx 364 (p100)
        if (lane == 5)  q[1] = v[11];   // idx 357 (p98)
        if (lane == 22) q[2] = v[5];    // idx 182 (p50)
        if (lane == 13) q[3] = v[3];    // idx 109 (p30)
        if (lane == 7)  q[4] = v[0];    // idx 7   (p2)
    }
    // ---- obs series for this site ----
    {
        float v[16]; float sum = 0.f;
        #pragma unroll
        for (int k = 0; k < 16; k++) {
            int e = k * 32 + lane;
            float x = (e < DAYS) ? so[e * 33 + w] : INF;
            v[k] = x;
            if (e < DAYS) sum += x;
        }
        #pragma unroll
        for (int o = 16; o; o >>= 1) sum += __shfl_xor_sync(0xffffffffu, sum, o);
        if (lane == 0) g_tM[oMY] = sum / (float)DAYS;
        bitonic512(v, lane);
        float* q = &g_tQ[oMY * 5];
        if (lane == 12) q[0] = v[11];
        if (lane == 5)  q[1] = v[11];
        if (lane == 22) q[2] = v[5];
        if (lane == 13) q[3] = v[3];
        if (lane == 7)  q[4] = v[0];
    }
}

// ---------------- kernel C: Theil-Sen medians + trend accumulation ----------------
// one warp per (site, stat q in 0..5); q=0 -> yearly means, q>=1 -> quantile q-1.
__global__ void __launch_bounds__(256)
theil_kernel() {
    const int gw   = (blockIdx.x * 256 + threadIdx.x) >> 5;  // 0 .. S*6-1 exactly
    const int lane = threadIdx.x & 31;
    const int s = gw / 6;
    const int q = gw % 6;

    float xP = 0.f, xT = 0.f;
    if (lane < N_YEARS) {
        if (q == 0) {
            xP = g_pM[s * N_YEARS + lane];
            xT = g_tM[s * N_YEARS + lane];
        } else {
            xP = g_pQ[(s * N_YEARS + lane) * 5 + (q - 1)];
            xT = g_tQ[(s * N_YEARS + lane) * 5 + (q - 1)];
        }
    }

    const float INF = __int_as_float(0x7f800000);
    float medP, medT;
    {
        float d[16];
        #pragma unroll
        for (int k = 0; k < 16; k++) {
            int e = k * 32 + lane;
            int idx = (e < NPAIRS) ? e : 0;
            int pi = g_pairI[idx], pj = g_pairJ[idx];
            float xi = __shfl_sync(0xffffffffu, xP, pi);
            float xj = __shfl_sync(0xffffffffu, xP, pj);
            d[k] = (e < NPAIRS) ? (xj - xi) / (float)(pj - pi) : INF;
        }
        bitonic512(d, lane);
        medP = d[6];   // element 217 lives on lane 25, reg 6
        #pragma unroll
        for (int k = 0; k < 16; k++) {
            int e = k * 32 + lane;
            int idx = (e < NPAIRS) ? e : 0;
            int pi = g_pairI[idx], pj = g_pairJ[idx];
            float xi = __shfl_sync(0xffffffffu, xT, pi);
            float xj = __shfl_sync(0xffffffffu, xT, pj);
            d[k] = (e < NPAIRS) ? (xj - xi) / (float)(pj - pi) : INF;
        }
        bitonic512(d, lane);
        medT = d[6];
    }

    if (lane == 25) {
        if (q == 0) {
            float df = medT - medP;
            atomicAdd(&g_mean_trend, (double)(df * df));
        } else {
            float r = medT / (-medP);
            atomicAdd(&g_quant_trend, (double)(r * r));
        }
    }
}

// ---------------- finalize ----------------
__global__ void finalize_kernel(float* out) {
    double mean = g_sumsq / (double)((long long)T_DAYS * (long long)S_SITES);
    float rmse = sqrtf((float)mean);
    out[0] = rmse + (float)((g_mean_trend + g_quant_trend) / (double)S_SITES);
}

// ---------------- launch ----------------
extern "C" void kernel_launch(void* const* d_in, const int* in_sizes, int n_in,
                              void* d_out, int out_size) {
    const float* y_pred = (const float*)d_in[0];
    const float* y_obs  = (const float*)d_in[1];
    float* out = (float*)d_out;

    const int smem_bytes = 2 * DAYS * 33 * (int)sizeof(float);   // 96360
    cudaFuncSetAttribute(stats_kernel,
                         cudaFuncAttributeMaxDynamicSharedMemorySize, smem_bytes);

    init_kernel<<<1, 32>>>();
    dim3 gridB(S_SITES / 32, N_YEARS);           // 125 x 30
    stats_kernel<<<gridB, 1024, smem_bytes>>>(y_pred, y_obs);
    theil_kernel<<<(S_SITES * 6) / 8, 256>>>();  // 3000 blocks, 8 warps each
    finalize_kernel<<<1, 1>>>(out);
}

// round 2
// speedup vs baseline: 1.0982x; 1.0982x over previous
#include <cuda_runtime.h>
#include <math.h>

#define T_DAYS   10950
#define S_SITES  4000
#define N_YEARS  30
#define DAYS     365
#define NPAIRS   435   // 30*29/2
// contiguous layout: element e = lane*16 + k
// ranks: 364=(l22,k12) 357=(l22,k5) 182=(l11,k6) 109=(l6,k13) 7=(l0,k7); median 217=(l13,k9)

// ---------------- scratch (device globals; no allocations) ----------------
__device__ double g_sumsq;
__device__ double g_mean_trend;
__device__ double g_quant_trend;
__device__ float  g_pM[S_SITES * N_YEARS];
__device__ float  g_tM[S_SITES * N_YEARS];
__device__ float  g_pQ[S_SITES * N_YEARS * 5];
__device__ float  g_tQ[S_SITES * N_YEARS * 5];
__device__ int    g_pairT[512];   // transposed: entry e at (e&15)*32 + (e>>4), packed i | j<<5
__device__ float  g_rcpT[512];    // 1/(j-i), same transposed slotting

// ---------------- float <-> order-preserving uint ----------------
__device__ __forceinline__ unsigned enc(float x) {
    unsigned f = __float_as_uint(x);
    return f ^ ((unsigned)((int)f >> 31) | 0x80000000u);
}
__device__ __forceinline__ float dec(unsigned u) {
    return __uint_as_float(u ^ ((~(unsigned)((int)u >> 31)) | 0x80000000u));
}

// ---------------- comparators (uint domain) ----------------
// hi = a+b-lo is exact under wraparound; adds split across fma/alu pipes by ptxas
__device__ __forceinline__ void cexg(unsigned &a, unsigned &b) {   // ascending
    unsigned lo = min(a, b); unsigned hi = a + b - lo; a = lo; b = hi;
}
__device__ __forceinline__ void cexgd(unsigned &a, unsigned &b) {  // descending
    unsigned lo = min(a, b); unsigned hi = a + b - lo; a = hi; b = lo;
}

// per-thread ascending bitonic sort of 16 registers (all directions compile-time)
__device__ __forceinline__ void sort16(unsigned v[16]) {
    #pragma unroll
    for (int size = 2; size <= 16; size <<= 1)
        #pragma unroll
        for (int stride = size >> 1; stride; stride >>= 1)
            #pragma unroll
            for (int k = 0; k < 16; k++)
                if (!(k & stride)) {
                    if (size == 16 || !(k & size)) cexg(v[k], v[k | stride]);
                    else                           cexgd(v[k], v[k | stride]);
                }
}

// merge level LM: merge ascending runs spanning 2^(LM-1) lanes into 2^LM lanes.
// mirror exchange (reverse trick) keeps every comparator ascending; the
// min-vs-max choice is a once-per-round uniform predicate -> predicated IMNMX.
template<int LM>
__device__ __forceinline__ void merge_level(unsigned v[16], int lane) {
    unsigned t[16];
    #pragma unroll
    for (int k = 0; k < 16; k++)
        t[k] = __shfl_xor_sync(0xffffffffu, v[15 - k], (1 << LM) - 1);
    bool lowh = (lane & (1 << (LM - 1))) == 0;
    #pragma unroll
    for (int k = 0; k < 16; k++)
        v[k] = lowh ? min(v[k], t[k]) : max(v[k], t[k]);
    #pragma unroll
    for (int s = LM - 2; s >= 0; s--) {
        bool lo_ = (lane & (1 << s)) == 0;
        #pragma unroll
        for (int k = 0; k < 16; k++) {
            unsigned o = __shfl_xor_sync(0xffffffffu, v[k], 1 << s);
            v[k] = lo_ ? min(v[k], o) : max(v[k], o);
        }
    }
    #pragma unroll
    for (int stride = 8; stride >= 1; stride >>= 1)
        #pragma unroll
        for (int k = 0; k < 16; k++)
            if (!(k & stride)) cexg(v[k], v[k | stride]);
}

__device__ __forceinline__ void sort512u(unsigned v[16], int lane) {
    sort16(v);
    merge_level<1>(v, lane);
    merge_level<2>(v, lane);
    merge_level<3>(v, lane);
    merge_level<4>(v, lane);
    merge_level<5>(v, lane);
}

// ---------------- init ----------------
__global__ void init_kernel() {
    int t = threadIdx.x;
    if (t == 0) { g_sumsq = 0.0; g_mean_trend = 0.0; g_quant_trend = 0.0; }
    if (t < 512) {
        int pk = 0; float rc = 0.f;
        if (t < NPAIRS) {
            int e = t, i = 0, cnt = N_YEARS - 1;
            while (e >= cnt) { e -= cnt; i++; cnt--; }
            int j = i + 1 + e;
            pk = i | (j << 5);
            rc = 1.0f / (float)(j - i);
        }
        g_pairT[(t & 15) * 32 + (t >> 4)] = pk;
        g_rcpT [(t & 15) * 32 + (t >> 4)] = rc;
    }
}

// ---------------- stats: fused rmse + per-(site,year) sort/stats ----------------
// grid (S/32, 30); 1024 threads. smem: two [365][32] tiles with diagonal swizzle
// addr(d,j) = d*32 + ((j + (d>>4)) & 31)  -> conflict-free writes AND reads.
__global__ void __launch_bounds__(1024, 1)
stats_kernel(const float* __restrict__ pred, const float* __restrict__ obs) {
    extern __shared__ float smem[];
    float* sp = smem;
    float* so = smem + DAYS * 32;

    const int tid  = threadIdx.x;
    const int lane = tid & 31;
    const int w    = tid >> 5;
    const int base = blockIdx.x * 32;
    const int year = blockIdx.y;

    float acc = 0.f;
    for (int i = tid; i < DAYS * 32; i += 1024) {
        int d = i >> 5, j = i & 31;
        int g = (year * DAYS + d) * S_SITES + base + j;
        float pv = pred[g], ov = obs[g];
        float df = pv - ov;
        acc += df * df;
        int a = d * 32 + ((j + (d >> 4)) & 31);
        sp[a] = pv;
        so[a] = ov;
    }
    #pragma unroll
    for (int o = 16; o; o >>= 1) acc += __shfl_xor_sync(0xffffffffu, acc, o);
    __shared__ float red[32];
    if (lane == 0) red[w] = acc;
    __syncthreads();                       // tiles ready + red ready
    if (w == 0) {
        float a = red[lane];
        #pragma unroll
        for (int o = 16; o; o >>= 1) a += __shfl_xor_sync(0xffffffffu, a, o);
        if (lane == 0) atomicAdd(&g_sumsq, (double)a);
    }

    const int site = base + w;
    const int col  = (w + lane) & 31;      // diagonal read column
    const int oMY  = site * N_YEARS + year;

    // ---- pred series ----
    {
        unsigned v[16]; float sum = 0.f;
        #pragma unroll
        for (int k = 0; k < 16; k++) {
            int e = lane * 16 + k;
            if (e < DAYS) { float x = sp[e * 32 + col]; sum += x; v[k] = enc(x); }
            else v[k] = 0xFFFFFFFFu;
        }
        #pragma unroll
        for (int o = 16; o; o >>= 1) sum += __shfl_xor_sync(0xffffffffu, sum, o);
        if (lane == 0) g_pM[oMY] = sum / (float)DAYS;
        sort512u(v, lane);
        float* q = &g_pQ[oMY * 5];
        if (lane == 22) { q[0] = dec(v[12]); q[1] = dec(v[5]); }
        if (lane == 11) q[2] = dec(v[6]);
        if (lane == 6)  q[3] = dec(v[13]);
        if (lane == 0)  q[4] = dec(v[7]);
    }
    // ---- obs series ----
    {
        unsigned v[16]; float sum = 0.f;
        #pragma unroll
        for (int k = 0; k < 16; k++) {
            int e = lane * 16 + k;
            if (e < DAYS) { float x = so[e * 32 + col]; sum += x; v[k] = enc(x); }
            else v[k] = 0xFFFFFFFFu;
        }
        #pragma unroll
        for (int o = 16; o; o >>= 1) sum += __shfl_xor_sync(0xffffffffu, sum, o);
        if (lane == 0) g_tM[oMY] = sum / (float)DAYS;
        sort512u(v, lane);
        float* q = &g_tQ[oMY * 5];
        if (lane == 22) { q[0] = dec(v[12]); q[1] = dec(v[5]); }
        if (lane == 11) q[2] = dec(v[6]);
        if (lane == 6)  q[3] = dec(v[13]);
        if (lane == 0)  q[4] = dec(v[7]);
    }
}

// ---------------- theil: medians of pairwise slopes + trend sums ----------------
// one warp per (site, stat q in 0..5)
__global__ void __launch_bounds__(256)
theil_kernel() {
    __shared__ int   s_pair[512];
    __shared__ float s_rcp[512];
    for (int i = threadIdx.x; i < 512; i += 256) {
        s_pair[i] = g_pairT[i];
        s_rcp[i]  = g_rcpT[i];
    }
    __syncthreads();

    const int gw   = (blockIdx.x * 256 + threadIdx.x) >> 5;  // 0 .. S*6-1
    const int lane = threadIdx.x & 31;
    const int s = gw / 6;
    const int q = gw % 6;

    float xP = 0.f, xT = 0.f;
    if (lane < N_YEARS) {
        if (q == 0) {
            xP = g_pM[s * N_YEARS + lane];
            xT = g_tM[s * N_YEARS + lane];
        } else {
            xP = g_pQ[(s * N_YEARS + lane) * 5 + (q - 1)];
            xT = g_tQ[(s * N_YEARS + lane) * 5 + (q - 1)];
        }
    }

    float medP, medT;
    {
        unsigned v[16];
        #pragma unroll
        for (int k = 0; k < 16; k++) {
            int idx = k * 32 + lane;           // transposed slot for e = lane*16+k
            int pk  = s_pair[idx];
            float rc = s_rcp[idx];
            float xi = __shfl_sync(0xffffffffu, xP, pk & 31);
            float xj = __shfl_sync(0xffffffffu, xP, (pk >> 5) & 31);
            int e = lane * 16 + k;
            v[k] = (e < NPAIRS) ? enc((xj - xi) * rc) : 0xFFFFFFFFu;
        }
        sort512u(v, lane);
        medP = dec(v[9]);                       // valid on lane 13
        #pragma unroll
        for (int k = 0; k < 16; k++) {
            int idx = k * 32 + lane;
            int pk  = s_pair[idx];
            float rc = s_rcp[idx];
            float xi = __shfl_sync(0xffffffffu, xT, pk & 31);
            float xj = __shfl_sync(0xffffffffu, xT, (pk >> 5) & 31);
            int e = lane * 16 + k;
            v[k] = (e < NPAIRS) ? enc((xj - xi) * rc) : 0xFFFFFFFFu;
        }
        sort512u(v, lane);
        medT = dec(v[9]);
    }

    if (lane == 13) {
        if (q == 0) {
            float df = medT - medP;
            atomicAdd(&g_mean_trend, (double)(df * df));
        } else {
            float r = medT / (-medP);
            atomicAdd(&g_quant_trend, (double)(r * r));
        }
    }
}

// ---------------- finalize ----------------
__global__ void finalize_kernel(float* out) {
    double mean = g_sumsq / (double)((long long)T_DAYS * (long long)S_SITES);
    float rmse = sqrtf((float)mean);
    out[0] = rmse + (float)((g_mean_trend + g_quant_trend) / (double)S_SITES);
}

// ---------------- launch ----------------
extern "C" void kernel_launch(void* const* d_in, const int* in_sizes, int n_in,
                              void* d_out, int out_size) {
    const float* y_pred = (const float*)d_in[0];
    const float* y_obs  = (const float*)d_in[1];
    float* out = (float*)d_out;

    const int smem_bytes = 2 * DAYS * 32 * (int)sizeof(float);   // 93440
    cudaFuncSetAttribute(stats_kernel,
                         cudaFuncAttributeMaxDynamicSharedMemorySize, smem_bytes);

    init_kernel<<<1, 512>>>();
    dim3 gridB(S_SITES / 32, N_YEARS);           // 125 x 30
    stats_kernel<<<gridB, 1024, smem_bytes>>>(y_pred, y_obs);
    theil_kernel<<<(S_SITES * 6) / 8, 256>>>();  // 3000 blocks
    finalize_kernel<<<1, 1>>>(out);
}

// round 5
// speedup vs baseline: 1.2717x; 1.1581x over previous
#include <cuda_runtime.h>
#include <math.h>

#define T_DAYS   10950
#define S_SITES  4000
#define N_YEARS  30
#define DAYS     365
#define NPAIRS   435   // 30*29/2
// contiguous layout: element e = lane*16 + k
// ranks: 364=(l22,k12) 357=(l22,k5) 182=(l11,k6) 109=(l6,k13) 7=(l0,k7); median 217=(l13,k9)

// ---------------- scratch (device globals; no allocations) ----------------
__device__ double g_sumsq;
__device__ double g_mean_trend;
__device__ double g_quant_trend;
__device__ float  g_pM[S_SITES * N_YEARS];
__device__ float  g_tM[S_SITES * N_YEARS];
__device__ float  g_pQ[S_SITES * N_YEARS * 5];
__device__ float  g_tQ[S_SITES * N_YEARS * 5];
__device__ int    g_pairT[512];   // transposed: entry e at (e&15)*32 + (e>>4), packed i | j<<5
__device__ float  g_rcpT[512];    // 1/(j-i), same transposed slotting

// ---------------- float <-> order-preserving uint ----------------
__device__ __forceinline__ unsigned enc(float x) {
    unsigned f = __float_as_uint(x);
    return f ^ ((unsigned)((int)f >> 31) | 0x80000000u);
}
__device__ __forceinline__ float dec(unsigned u) {
    return __uint_as_float(u ^ ((~(unsigned)((int)u >> 31)) | 0x80000000u));
}

// ---------------- comparators (uint domain) ----------------
// hi = a+b-lo is exact under wraparound (single IADD3); lo = IMNMX
__device__ __forceinline__ void cexg(unsigned &a, unsigned &b) {   // ascending
    unsigned lo = min(a, b); unsigned hi = a + b - lo; a = lo; b = hi;
}
__device__ __forceinline__ void cexgd(unsigned &a, unsigned &b) {  // descending
    unsigned lo = min(a, b); unsigned hi = a + b - lo; a = hi; b = lo;
}

// per-thread ascending bitonic sort of 16 registers (all directions compile-time)
__device__ __forceinline__ void sort16(unsigned v[16]) {
    #pragma unroll
    for (int size = 2; size <= 16; size <<= 1)
        #pragma unroll
        for (int stride = size >> 1; stride; stride >>= 1)
            #pragma unroll
            for (int k = 0; k < 16; k++)
                if (!(k & stride)) {
                    if (size == 16 || !(k & size)) cexg(v[k], v[k | stride]);
                    else                           cexgd(v[k], v[k | stride]);
                }
}

// merge level LM: merge ascending runs spanning 2^(LM-1) lanes into 2^LM lanes.
// mirror exchange done IN-PLACE on pairs (k, 15-k): no t[16] array -> low reg
// pressure. min/max choice is a uniform predicate -> predicated IMNMX.
template<int LM>
__device__ __forceinline__ void merge_level(unsigned v[16], int lane) {
    const unsigned mm = (1u << LM) - 1u;
    bool lowh = (lane & (1 << (LM - 1))) == 0;
    #pragma unroll
    for (int k = 0; k < 8; k++) {
        unsigned a = __shfl_xor_sync(0xffffffffu, v[15 - k], mm);  // partner of v[k]
        unsigned b = __shfl_xor_sync(0xffffffffu, v[k], mm);       // partner of v[15-k]
        v[k]      = lowh ? min(v[k], a)      : max(v[k], a);
        v[15 - k] = lowh ? min(v[15 - k], b) : max(v[15 - k], b);
    }
    #pragma unroll
    for (int s = LM - 2; s >= 0; s--) {
        bool lo_ = (lane & (1 << s)) == 0;
        #pragma unroll
        for (int k = 0; k < 16; k++) {
            unsigned o = __shfl_xor_sync(0xffffffffu, v[k], 1 << s);
            v[k] = lo_ ? min(v[k], o) : max(v[k], o);
        }
    }
    #pragma unroll
    for (int stride = 8; stride >= 1; stride >>= 1)
        #pragma unroll
        for (int k = 0; k < 16; k++)
            if (!(k & stride)) cexg(v[k], v[k | stride]);
}

__device__ __forceinline__ void sort512u(unsigned v[16], int lane) {
    sort16(v);
    merge_level<1>(v, lane);
    merge_level<2>(v, lane);
    merge_level<3>(v, lane);
    merge_level<4>(v, lane);
    merge_level<5>(v, lane);
}

// ---------------- init ----------------
__global__ void init_kernel() {
    int t = threadIdx.x;
    if (t == 0) { g_sumsq = 0.0; g_mean_trend = 0.0; g_quant_trend = 0.0; }
    if (t < 512) {
        int pk = 0; float rc = 0.f;
        if (t < NPAIRS) {
            int e = t, i = 0, cnt = N_YEARS - 1;
            while (e >= cnt) { e -= cnt; i++; cnt--; }
            int j = i + 1 + e;
            pk = i | (j << 5);
            rc = 1.0f / (float)(j - i);
        }
        g_pairT[(t & 15) * 32 + (t >> 4)] = pk;
        g_rcpT [(t & 15) * 32 + (t >> 4)] = rc;
    }
}

// ---------------- stats: fused rmse + per-(site,year) sort/stats ----------------
// grid (S/32, 30); 512 threads (16 warps). Each warp sorts 2 sites sequentially.
// smem: two [365][32] tiles, diagonal swizzle addr(d,j) = d*32 + ((j + (d>>4)) & 31)
// -> conflict-free writes AND column reads (e>>4 == lane for e = lane*16+k).
// 512 thr => 128-reg cap: no spills.
__global__ void __launch_bounds__(512)
stats_kernel(const float* __restrict__ pred, const float* __restrict__ obs) {
    extern __shared__ float smem[];
    float* sp = smem;
    float* so = smem + DAYS * 32;

    const int tid  = threadIdx.x;
    const int lane = tid & 31;
    const int w    = tid >> 5;
    const int base = blockIdx.x * 32;
    const int year = blockIdx.y;

    float acc = 0.f;
    for (int i = tid; i < DAYS * 32; i += 512) {
        int d = i >> 5, j = i & 31;
        int g = (year * DAYS + d) * S_SITES + base + j;
        float pv = pred[g], ov = obs[g];
        float df = pv - ov;
        acc += df * df;
        int a = d * 32 + ((j + (d >> 4)) & 31);
        sp[a] = pv;
        so[a] = ov;
    }
    #pragma unroll
    for (int o = 16; o; o >>= 1) acc += __shfl_xor_sync(0xffffffffu, acc, o);
    __shared__ float red[16];
    if (lane == 0) red[w] = acc;
    __syncthreads();                       // tiles ready + red ready
    if (w == 0) {                          // FULL warp participates (fix for R4 UB)
        float a = (lane < 16) ? red[lane] : 0.f;
        #pragma unroll
        for (int o = 16; o; o >>= 1) a += __shfl_xor_sync(0xffffffffu, a, o);
        if (lane == 0) atomicAdd(&g_sumsq, (double)a);
    }

    #pragma unroll
    for (int sub = 0; sub < 2; sub++) {
        const int sl   = w + sub * 16;             // site-local 0..31
        const int site = base + sl;
        const int col  = (sl + lane) & 31;         // diagonal read column
        const int oMY  = site * N_YEARS + year;

        // ---- pred series ----
        {
            unsigned v[16]; float sum = 0.f;
            #pragma unroll
            for (int k = 0; k < 16; k++) {
                int e = lane * 16 + k;
                if (e < DAYS) { float x = sp[e * 32 + col]; sum += x; v[k] = enc(x); }
                else v[k] = 0xFFFFFFFFu;
            }
            #pragma unroll
            for (int o = 16; o; o >>= 1) sum += __shfl_xor_sync(0xffffffffu, sum, o);
            if (lane == 0) g_pM[oMY] = sum / (float)DAYS;
            sort512u(v, lane);
            float* q = &g_pQ[oMY * 5];
            if (lane == 22) { q[0] = dec(v[12]); q[1] = dec(v[5]); }
            if (lane == 11) q[2] = dec(v[6]);
            if (lane == 6)  q[3] = dec(v[13]);
            if (lane == 0)  q[4] = dec(v[7]);
        }
        // ---- obs series ----
        {
            unsigned v[16]; float sum = 0.f;
            #pragma unroll
            for (int k = 0; k < 16; k++) {
                int e = lane * 16 + k;
                if (e < DAYS) { float x = so[e * 32 + col]; sum += x; v[k] = enc(x); }
                else v[k] = 0xFFFFFFFFu;
            }
            #pragma unroll
            for (int o = 16; o; o >>= 1) sum += __shfl_xor_sync(0xffffffffu, sum, o);
            if (lane == 0) g_tM[oMY] = sum / (float)DAYS;
            sort512u(v, lane);
            float* q = &g_tQ[oMY * 5];
            if (lane == 22) { q[0] = dec(v[12]); q[1] = dec(v[5]); }
            if (lane == 11) q[2] = dec(v[6]);
            if (lane == 6)  q[3] = dec(v[13]);
            if (lane == 0)  q[4] = dec(v[7]);
        }
    }
}

// ---------------- theil: medians of pairwise slopes + trend sums ----------------
// one warp per (site, stat q in 0..5)
__global__ void __launch_bounds__(256)
theil_kernel() {
    __shared__ int   s_pair[512];
    __shared__ float s_rcp[512];
    for (int i = threadIdx.x; i < 512; i += 256) {
        s_pair[i] = g_pairT[i];
        s_rcp[i]  = g_rcpT[i];
    }
    __syncthreads();

    const int gw   = (blockIdx.x * 256 + threadIdx.x) >> 5;  // 0 .. S*6-1
    const int lane = threadIdx.x & 31;
    const int s = gw / 6;
    const int q = gw % 6;

    float xP = 0.f, xT = 0.f;
    if (lane < N_YEARS) {
        if (q == 0) {
            xP = g_pM[s * N_YEARS + lane];
            xT = g_tM[s * N_YEARS + lane];
        } else {
            xP = g_pQ[(s * N_YEARS + lane) * 5 + (q - 1)];
            xT = g_tQ[(s * N_YEARS + lane) * 5 + (q - 1)];
        }
    }

    float medP, medT;
    {
        unsigned v[16];
        #pragma unroll
        for (int k = 0; k < 16; k++) {
            int idx = k * 32 + lane;           // transposed slot for e = lane*16+k
            int pk  = s_pair[idx];
            float rc = s_rcp[idx];
            float xi = __shfl_sync(0xffffffffu, xP, pk & 31);
            float xj = __shfl_sync(0xffffffffu, xP, (pk >> 5) & 31);
            int e = lane * 16 + k;
            v[k] = (e < NPAIRS) ? enc((xj - xi) * rc) : 0xFFFFFFFFu;
        }
        sort512u(v, lane);
        medP = dec(v[9]);                       // element 217 lives on lane 13, reg 9
        #pragma unroll
        for (int k = 0; k < 16; k++) {
            int idx = k * 32 + lane;
            int pk  = s_pair[idx];
            float rc = s_rcp[idx];
            float xi = __shfl_sync(0xffffffffu, xT, pk & 31);
            float xj = __shfl_sync(0xffffffffu, xT, (pk >> 5) & 31);
            int e = lane * 16 + k;
            v[k] = (e < NPAIRS) ? enc((xj - xi) * rc) : 0xFFFFFFFFu;
        }
        sort512u(v, lane);
        medT = dec(v[9]);
    }

    if (lane == 13) {
        if (q == 0) {
            float df = medT - medP;
            atomicAdd(&g_mean_trend, (double)(df * df));
        } else {
            float r = medT / (-medP);
            atomicAdd(&g_quant_trend, (double)(r * r));
        }
    }
}

// ---------------- finalize ----------------
__global__ void finalize_kernel(float* out) {
    double mean = g_sumsq / (double)((long long)T_DAYS * (long long)S_SITES);
    float rmse = sqrtf((float)mean);
    out[0] = rmse + (float)((g_mean_trend + g_quant_trend) / (double)S_SITES);
}

// ---------------- launch ----------------
extern "C" void kernel_launch(void* const* d_in, const int* in_sizes, int n_in,
                              void* d_out, int out_size) {
    const float* y_pred = (const float*)d_in[0];
    const float* y_obs  = (const float*)d_in[1];
    float* out = (float*)d_out;

    const int smem_bytes = 2 * DAYS * 32 * (int)sizeof(float);   // 93440
    cudaFuncSetAttribute(stats_kernel,
                         cudaFuncAttributeMaxDynamicSharedMemorySize, smem_bytes);

    init_kernel<<<1, 512>>>();
    dim3 gridB(S_SITES / 32, N_YEARS);           // 125 x 30
    stats_kernel<<<gridB, 512, smem_bytes>>>(y_pred, y_obs);
    theil_kernel<<<(S_SITES * 6) / 8, 256>>>();  // 3000 blocks
    finalize_kernel<<<1, 1>>>(out);
}

// round 7
// speedup vs baseline: 1.4422x; 1.1341x over previous
#include <cuda_runtime.h>
#include <math.h>

#define T_DAYS   10950
#define S_SITES  4000
#define N_YEARS  30
#define DAYS     365
#define NPAIRS   435   // 30*29/2
// contiguous layout: element e = lane*16 + k. Sort stops at two 256-runs
// (lanes 0-15 / 16-31); exact ranks extracted via merge-path binary search.

// ---------------- scratch (device globals; no allocations) ----------------
__device__ double g_sumsq;
__device__ double g_mean_trend;
__device__ double g_quant_trend;
__device__ float  g_pM[S_SITES * N_YEARS];
__device__ float  g_tM[S_SITES * N_YEARS];
__device__ float  g_pQ[S_SITES * N_YEARS * 5];
__device__ float  g_tQ[S_SITES * N_YEARS * 5];
__device__ int    g_pairT[512];   // transposed: entry e at (e&15)*32 + (e>>4), packed i | j<<5
__device__ float  g_rcpT[512];    // 1/(j-i), same transposed slotting

// ---------------- float <-> order-preserving uint ----------------
__device__ __forceinline__ unsigned enc(float x) {
    unsigned f = __float_as_uint(x);
    return f ^ ((unsigned)((int)f >> 31) | 0x80000000u);
}
__device__ __forceinline__ float dec(unsigned u) {
    return __uint_as_float(u ^ ((~(unsigned)((int)u >> 31)) | 0x80000000u));
}

// ---------------- comparator (uint domain) ----------------
// lo = IMNMX; hi = a+b-lo exact under wraparound (IADD3/IMAD split across pipes)
__device__ __forceinline__ void cexg(unsigned &a, unsigned &b) {   // ascending
    unsigned lo = min(a, b); unsigned hi = a + b - lo; a = lo; b = hi;
}

// ---------------- Batcher odd-even merge sort of 16 regs (63 comparators) ----
template<int LO, int N, int R>
__device__ __forceinline__ void oes_merge(unsigned* v) {
    constexpr int M = R * 2;
    if constexpr (M < N) {
        oes_merge<LO, N, M>(v);
        oes_merge<LO + R, N, M>(v);
        #pragma unroll
        for (int i = LO + R; i + R < LO + N; i += M) cexg(v[i], v[i + R]);
    } else {
        cexg(v[LO], v[LO + R]);
    }
}
template<int LO, int N>
__device__ __forceinline__ void oes_sort(unsigned* v) {
    if constexpr (N > 1) {
        constexpr int M = N / 2;
        oes_sort<LO, M>(v);
        oes_sort<LO + M, M>(v);
        oes_merge<LO, N, 1>(v);
    }
}

// merge level LM: merge ascending runs spanning 2^(LM-1) lanes into 2^LM lanes.
// mirror exchange done IN-PLACE on pairs (k, 15-k): low reg pressure.
template<int LM>
__device__ __forceinline__ void merge_level(unsigned v[16], int lane) {
    const unsigned mm = (1u << LM) - 1u;
    bool lowh = (lane & (1 << (LM - 1))) == 0;
    #pragma unroll
    for (int k = 0; k < 8; k++) {
        unsigned a = __shfl_xor_sync(0xffffffffu, v[15 - k], mm);  // partner of v[k]
        unsigned b = __shfl_xor_sync(0xffffffffu, v[k], mm);       // partner of v[15-k]
        v[k]      = lowh ? min(v[k], a)      : max(v[k], a);
        v[15 - k] = lowh ? min(v[15 - k], b) : max(v[15 - k], b);
    }
    #pragma unroll
    for (int s = LM - 2; s >= 0; s--) {
        bool lo_ = (lane & (1 << s)) == 0;
        #pragma unroll
        for (int k = 0; k < 16; k++) {
            unsigned o = __shfl_xor_sync(0xffffffffu, v[k], 1 << s);
            v[k] = lo_ ? min(v[k], o) : max(v[k], o);
        }
    }
    #pragma unroll
    for (int stride = 8; stride >= 1; stride >>= 1)
        #pragma unroll
        for (int k = 0; k < 16; k++)
            if (!(k & stride)) cexg(v[k], v[k | stride]);
}

// sort up to two 256-runs: per-thread ascending run, then 4 cross-lane merges
__device__ __forceinline__ void sort_to_runs(unsigned v[16], int lane) {
    oes_sort<0, 16>(v);
    merge_level<1>(v, lane);
    merge_level<2>(v, lane);
    merge_level<3>(v, lane);
    merge_level<4>(v, lane);
}

// dump two 256-runs to smem (stride-1 dense -> conflict-free STS.128)
__device__ __forceinline__ void dump_runs(const unsigned v[16], unsigned* scr, int lane) {
    __syncwarp();                                  // prior readers done
    uint4* dst = reinterpret_cast<uint4*>(scr + lane * 16);
    dst[0] = make_uint4(v[0],  v[1],  v[2],  v[3]);
    dst[1] = make_uint4(v[4],  v[5],  v[6],  v[7]);
    dst[2] = make_uint4(v[8],  v[9],  v[10], v[11]);
    dst[3] = make_uint4(v[12], v[13], v[14], v[15]);
    __syncwarp();
}

// exact rank-r (0-indexed) of A[0..255] ∪ B[0..255], both ascending (uint domain)
__device__ __forceinline__ unsigned merge_path_rank(const unsigned* A, const unsigned* B, int r) {
    int lo = r - 255; if (lo < 0) lo = 0;
    int hi = r + 1;   if (hi > 256) hi = 256;
    while (lo < hi) {
        int a = (lo + hi) >> 1;                    // a <= 255 in-loop
        if (A[a] < B[r - a]) lo = a + 1; else hi = a;
    }
    int a = lo, bm = r - a;                        // b-1 = r-a
    unsigned va = (a > 0)   ? A[a - 1] : 0u;
    unsigned vb = (bm >= 0) ? B[bm]    : 0u;
    return max(va, vb);
}

// ---------------- init ----------------
__global__ void init_kernel() {
    int t = threadIdx.x;
    if (t == 0) { g_sumsq = 0.0; g_mean_trend = 0.0; g_quant_trend = 0.0; }
    if (t < 512) {
        int pk = 0; float rc = 0.f;
        if (t < NPAIRS) {
            int e = t, i = 0, cnt = N_YEARS - 1;
            while (e >= cnt) { e -= cnt; i++; cnt--; }
            int j = i + 1 + e;
            pk = i | (j << 5);
            rc = 1.0f / (float)(j - i);
        }
        g_pairT[(t & 15) * 32 + (t >> 4)] = pk;
        g_rcpT [(t & 15) * 32 + (t >> 4)] = rc;
    }
}

// per-site: mean + 5 exact order statistics
__device__ __forceinline__ void site_process(const float* tile, unsigned* scr,
                                             int sl, int lane,
                                             float* meanPtr, float* qPtr) {
    const int col = (sl + lane) & 31;              // diagonal read column
    unsigned v[16]; float sum = 0.f;
    #pragma unroll
    for (int k = 0; k < 16; k++) {
        int e = lane * 16 + k;
        if (e < DAYS) { float x = tile[e * 32 + col]; sum += x; v[k] = enc(x); }
        else v[k] = 0xFFFFFFFFu;
    }
    #pragma unroll
    for (int o = 16; o; o >>= 1) sum += __shfl_xor_sync(0xffffffffu, sum, o);
    if (lane == 0) *meanPtr = sum / (float)DAYS;
    sort_to_runs(v, lane);
    dump_runs(v, scr, lane);
    if (lane < 5) {
        int r = (lane == 0) ? 364 : (lane == 1) ? 357 :
                (lane == 2) ? 182 : (lane == 3) ? 109 : 7;
        unsigned val = merge_path_rank(scr, scr + 256, r);
        qPtr[lane] = dec(val);                     // q order matches PLIST
    }
}

// ---------------- stats: fused rmse + per-(site,year) stats ----------------
// grid (S/32, 30); 512 threads (16 warps), each warp handles 2 sites.
// smem: one [365][32] tile (diag swizzle) + 16x512 u32 scratch = 79488 B.
// Phase1: load pred tile + rmse (obs via LDG). Phase2: pred sorts.
// Phase3: reload obs into tile. Phase4: obs sorts.
__global__ void __launch_bounds__(512)
stats_kernel(const float* __restrict__ pred, const float* __restrict__ obs) {
    extern __shared__ float smem[];
    float*    sp  = smem;
    unsigned* scr = reinterpret_cast<unsigned*>(smem + DAYS * 32);

    const int tid  = threadIdx.x;
    const int lane = tid & 31;
    const int w    = tid >> 5;
    const int base = blockIdx.x * 32;
    const int year = blockIdx.y;
    unsigned* myscr = scr + w * 512;

    // phase 1
    float acc = 0.f;
    for (int i = tid; i < DAYS * 32; i += 512) {
        int d = i >> 5, j = i & 31;
        int g = (year * DAYS + d) * S_SITES + base + j;
        float pv = pred[g], ov = obs[g];
        float df = pv - ov;
        acc += df * df;
        sp[d * 32 + ((j + (d >> 4)) & 31)] = pv;
    }
    #pragma unroll
    for (int o = 16; o; o >>= 1) acc += __shfl_xor_sync(0xffffffffu, acc, o);
    __shared__ float red[16];
    if (lane == 0) red[w] = acc;
    __syncthreads();                       // tile ready + red ready
    if (w == 0) {                          // full warp participates
        float a = (lane < 16) ? red[lane] : 0.f;
        #pragma unroll
        for (int o = 16; o; o >>= 1) a += __shfl_xor_sync(0xffffffffu, a, o);
        if (lane == 0) atomicAdd(&g_sumsq, (double)a);
    }

    // phase 2: pred stats
    #pragma unroll
    for (int sub = 0; sub < 2; sub++) {
        const int sl   = w + sub * 16;
        const int oMY  = (base + sl) * N_YEARS + year;
        site_process(sp, myscr, sl, lane, &g_pM[oMY], &g_pQ[oMY * 5]);
    }
    __syncthreads();                       // all pred reads done

    // phase 3: reload obs into the same tile
    for (int i = tid; i < DAYS * 32; i += 512) {
        int d = i >> 5, j = i & 31;
        int g = (year * DAYS + d) * S_SITES + base + j;
        sp[d * 32 + ((j + (d >> 4)) & 31)] = obs[g];
    }
    __syncthreads();

    // phase 4: obs stats
    #pragma unroll
    for (int sub = 0; sub < 2; sub++) {
        const int sl   = w + sub * 16;
        const int oMY  = (base + sl) * N_YEARS + year;
        site_process(sp, myscr, sl, lane, &g_tM[oMY], &g_tQ[oMY * 5]);
    }
}

// ---------------- theil: medians of pairwise slopes + trend sums ----------------
// one warp per (site, stat q in 0..5)
__global__ void __launch_bounds__(256)
theil_kernel() {
    __shared__ int   s_pair[512];
    __shared__ float s_rcp[512];
    __shared__ __align__(16) unsigned tscr[8 * 512];
    for (int i = threadIdx.x; i < 512; i += 256) {
        s_pair[i] = g_pairT[i];
        s_rcp[i]  = g_rcpT[i];
    }
    __syncthreads();

    const int gw   = (blockIdx.x * 256 + threadIdx.x) >> 5;  // 0 .. S*6-1
    const int lane = threadIdx.x & 31;
    const int s = gw / 6;
    const int q = gw % 6;
    unsigned* scr = tscr + (threadIdx.x >> 5) * 512;

    float xP = 0.f, xT = 0.f;
    if (lane < N_YEARS) {
        if (q == 0) {
            xP = g_pM[s * N_YEARS + lane];
            xT = g_tM[s * N_YEARS + lane];
        } else {
            xP = g_pQ[(s * N_YEARS + lane) * 5 + (q - 1)];
            xT = g_tQ[(s * N_YEARS + lane) * 5 + (q - 1)];
        }
    }

    float medP, medT;
    {
        unsigned v[16];
        #pragma unroll
        for (int k = 0; k < 16; k++) {
            int idx = k * 32 + lane;           // transposed slot for e = lane*16+k
            int pk  = s_pair[idx];
            float rc = s_rcp[idx];
            float xi = __shfl_sync(0xffffffffu, xP, pk & 31);
            float xj = __shfl_sync(0xffffffffu, xP, (pk >> 5) & 31);
            int e = lane * 16 + k;
            v[k] = (e < NPAIRS) ? enc((xj - xi) * rc) : 0xFFFFFFFFu;
        }
        sort_to_runs(v, lane);
        dump_runs(v, scr, lane);
        medP = (lane == 0) ? dec(merge_path_rank(scr, scr + 256, 217)) : 0.f;

        #pragma unroll
        for (int k = 0; k < 16; k++) {
            int idx = k * 32 + lane;
            int pk  = s_pair[idx];
            float rc = s_rcp[idx];
            float xi = __shfl_sync(0xffffffffu, xT, pk & 31);
            float xj = __shfl_sync(0xffffffffu, xT, (pk >> 5) & 31);
            int e = lane * 16 + k;
            v[k] = (e < NPAIRS) ? enc((xj - xi) * rc) : 0xFFFFFFFFu;
        }
        sort_to_runs(v, lane);
        dump_runs(v, scr, lane);
        medT = (lane == 0) ? dec(merge_path_rank(scr, scr + 256, 217)) : 0.f;
    }

    if (lane == 0) {
        if (q == 0) {
            float df = medT - medP;
            atomicAdd(&g_mean_trend, (double)(df * df));
        } else {
            float r = medT / (-medP);
            atomicAdd(&g_quant_trend, (double)(r * r));
        }
    }
}

// ---------------- finalize ----------------
__global__ void finalize_kernel(float* out) {
    double mean = g_sumsq / (double)((long long)T_DAYS * (long long)S_SITES);
    float rmse = sqrtf((float)mean);
    out[0] = rmse + (float)((g_mean_trend + g_quant_trend) / (double)S_SITES);
}

// ---------------- launch ----------------
extern "C" void kernel_launch(void* const* d_in, const int* in_sizes, int n_in,
                              void* d_out, int out_size) {
    const float* y_pred = (const float*)d_in[0];
    const float* y_obs  = (const float*)d_in[1];
    float* out = (float*)d_out;

    const int smem_bytes = (DAYS * 32 + 16 * 512) * (int)sizeof(float);   // 79488
    cudaFuncSetAttribute(stats_kernel,
                         cudaFuncAttributeMaxDynamicSharedMemorySize, smem_bytes);

    init_kernel<<<1, 512>>>();
    dim3 gridB(S_SITES / 32, N_YEARS);           // 125 x 30
    stats_kernel<<<gridB, 512, smem_bytes>>>(y_pred, y_obs);
    theil_kernel<<<(S_SITES * 6) / 8, 256>>>();  // 3000 blocks
    finalize_kernel<<<1, 1>>>(out);
}